// round 3
// baseline (speedup 1.0000x reference)
#include <cuda_runtime.h>

#define DIMC   1024
#define HEADS  16
#define HDIM   64
#define BATCH  4
#define SEQ    4096
#define M_TOT  (BATCH * SEQ)      // 16384 tokens
#define BHN    (BATCH * HEADS)    // 64
#define NSPLIT 8

// ---- scratch (static device globals; no runtime allocation) ----
__device__ float g_q[(size_t)M_TOT * DIMC];
__device__ float g_k[(size_t)M_TOT * DIMC];
__device__ float g_v[(size_t)M_TOT * DIMC];
__device__ float g_kvp[(size_t)BHN * NSPLIT * HDIM * HDIM];
__device__ float g_ksp[(size_t)BHN * NSPLIT * HDIM];
__device__ float g_kv[(size_t)BHN * HDIM * HDIM];
__device__ float g_ks[(size_t)BHN * HDIM];

// ============================================================================
// K1: projection GEMM.  out[m, n] = relu?( sum_k X[m,k] * W[n,k] + bias[n] )
// 128x128 block tile, 8x8 thread tile, BK=8, double-buffered smem.
// ============================================================================
__global__ __launch_bounds__(256) void qkv_gemm(
    const float* __restrict__ X, const float* __restrict__ W,
    const float* __restrict__ bias, float* __restrict__ out, int do_relu)
{
    __shared__ float As[2][8][132];
    __shared__ float Bs[2][8][132];
    const int K  = DIMC;
    const int m0 = blockIdx.y * 128;
    const int n0 = blockIdx.x * 128;
    const int t  = threadIdx.x;
    const int lrow = t >> 1;          // 0..127
    const int lk   = (t & 1) * 4;     // 0 or 4
    const float* Ap = X + (size_t)(m0 + lrow) * K + lk;
    const float* Bp = W + (size_t)(n0 + lrow) * K + lk;
    const int tx = t & 15;
    const int ty = t >> 4;

    float acc[8][8];
#pragma unroll
    for (int i = 0; i < 8; i++)
#pragma unroll
        for (int j = 0; j < 8; j++) acc[i][j] = 0.f;

    float4 ar = *(const float4*)Ap;
    float4 br = *(const float4*)Bp;
    int buf = 0;

    for (int kt = 0; kt < K; kt += 8) {
        As[buf][lk + 0][lrow] = ar.x;
        As[buf][lk + 1][lrow] = ar.y;
        As[buf][lk + 2][lrow] = ar.z;
        As[buf][lk + 3][lrow] = ar.w;
        Bs[buf][lk + 0][lrow] = br.x;
        Bs[buf][lk + 1][lrow] = br.y;
        Bs[buf][lk + 2][lrow] = br.z;
        Bs[buf][lk + 3][lrow] = br.w;
        __syncthreads();
        if (kt + 8 < K) {
            ar = *(const float4*)(Ap + kt + 8);
            br = *(const float4*)(Bp + kt + 8);
        }
#pragma unroll
        for (int kk = 0; kk < 8; kk++) {
            float4 a0 = *(const float4*)&As[buf][kk][ty * 8];
            float4 a1 = *(const float4*)&As[buf][kk][ty * 8 + 4];
            float4 b0 = *(const float4*)&Bs[buf][kk][tx * 8];
            float4 b1 = *(const float4*)&Bs[buf][kk][tx * 8 + 4];
            float a[8] = {a0.x, a0.y, a0.z, a0.w, a1.x, a1.y, a1.z, a1.w};
            float b[8] = {b0.x, b0.y, b0.z, b0.w, b1.x, b1.y, b1.z, b1.w};
#pragma unroll
            for (int i = 0; i < 8; i++)
#pragma unroll
                for (int j = 0; j < 8; j++)
                    acc[i][j] = fmaf(a[i], b[j], acc[i][j]);
        }
        buf ^= 1;
    }

    // epilogue: bias (+relu), vectorized stores
    float bv[8];
#pragma unroll
    for (int j = 0; j < 8; j++) bv[j] = bias[n0 + tx * 8 + j];
#pragma unroll
    for (int i = 0; i < 8; i++) {
        float r[8];
#pragma unroll
        for (int j = 0; j < 8; j++) {
            float v = acc[i][j] + bv[j];
            r[j] = do_relu ? fmaxf(v, 0.f) : v;
        }
        float* o = out + (size_t)(m0 + ty * 8 + i) * DIMC + n0 + tx * 8;
        *(float4*)(o)     = make_float4(r[0], r[1], r[2], r[3]);
        *(float4*)(o + 4) = make_float4(r[4], r[5], r[6], r[7]);
    }
}

// ============================================================================
// K2: partial kv[d][p] = sum_n k[n,d]*v[n,p], partial k_sum[d], per (b,h,split)
// ============================================================================
__global__ __launch_bounds__(256) void kv_partial(
    const float* __restrict__ gk, const float* __restrict__ gv)
{
    const int sp = blockIdx.x;          // 0..7
    const int bh = blockIdx.y;          // 0..63
    const int b = bh >> 4, h = bh & 15;
    __shared__ float ks[8][64];
    __shared__ float vs[8][64];
    const int t = threadIdx.x;
    const int tr = t >> 4;              // 0..15 (d group)
    const int tc = t & 15;              // 0..15 (p group)

    float acc[4][4];
#pragma unroll
    for (int i = 0; i < 4; i++)
#pragma unroll
        for (int j = 0; j < 4; j++) acc[i][j] = 0.f;
    float ksum = 0.f;

    const size_t base = ((size_t)b * SEQ) * DIMC + (size_t)h * HDIM;
    const int n0 = sp * (SEQ / NSPLIT);

    for (int nn = n0; nn < n0 + SEQ / NSPLIT; nn += 8) {
        {
            int e0 = t,       r0_ = e0 >> 6, c0_ = e0 & 63;
            int e1 = t + 256, r1_ = e1 >> 6, c1_ = e1 & 63;
            size_t g0 = base + (size_t)(nn + r0_) * DIMC + c0_;
            size_t g1 = base + (size_t)(nn + r1_) * DIMC + c1_;
            ks[r0_][c0_] = gk[g0];
            vs[r0_][c0_] = gv[g0];
            ks[r1_][c1_] = gk[g1];
            vs[r1_][c1_] = gv[g1];
        }
        __syncthreads();
#pragma unroll
        for (int r = 0; r < 8; r++) {
            float kd[4], vd[4];
#pragma unroll
            for (int i = 0; i < 4; i++) kd[i] = ks[r][tr * 4 + i];
#pragma unroll
            for (int j = 0; j < 4; j++) vd[j] = vs[r][tc * 4 + j];
#pragma unroll
            for (int i = 0; i < 4; i++)
#pragma unroll
                for (int j = 0; j < 4; j++)
                    acc[i][j] = fmaf(kd[i], vd[j], acc[i][j]);
        }
        if (t < 64) {
#pragma unroll
            for (int r = 0; r < 8; r++) ksum += ks[r][t];
        }
        __syncthreads();
    }

    float* o = g_kvp + ((size_t)bh * NSPLIT + sp) * (HDIM * HDIM);
#pragma unroll
    for (int i = 0; i < 4; i++)
#pragma unroll
        for (int j = 0; j < 4; j++)
            o[(tr * 4 + i) * HDIM + tc * 4 + j] = acc[i][j];
    if (t < 64) g_ksp[((size_t)bh * NSPLIT + sp) * HDIM + t] = ksum;
}

// ============================================================================
// K2b: reduce partials
// ============================================================================
__global__ __launch_bounds__(256) void kv_reduce()
{
    const int bh = blockIdx.x;
    const int t = threadIdx.x;
    for (int e = t; e < HDIM * HDIM; e += 256) {
        float s = 0.f;
#pragma unroll
        for (int sp = 0; sp < NSPLIT; sp++)
            s += g_kvp[((size_t)bh * NSPLIT + sp) * (HDIM * HDIM) + e];
        g_kv[(size_t)bh * (HDIM * HDIM) + e] = s;
    }
    if (t < HDIM) {
        float s = 0.f;
#pragma unroll
        for (int sp = 0; sp < NSPLIT; sp++)
            s += g_ksp[((size_t)bh * NSPLIT + sp) * HDIM + t];
        g_ks[(size_t)bh * HDIM + t] = s;
    }
}

// ============================================================================
// K3: ctx[n,p] = sum_d q[n,d]*kv[d,p];  denom = max(q . k_sum, 1e-6);
//     writes ctx/denom into d_out laid out as (B,N,H,HD)
// 64-token tiles per block; kv + q tile staged in smem.
// ============================================================================
__global__ __launch_bounds__(256) void ctx_kernel(
    const float* __restrict__ gq, float* __restrict__ out)
{
    const int bh = blockIdx.y;
    const int b = bh >> 4, h = bh & 15;
    const int n0 = blockIdx.x * 64;
    __shared__ float KVs[64][64];
    __shared__ float Qs[64][64];
    __shared__ float sks[64];
    __shared__ float dn[64];
    const int t = threadIdx.x;

    for (int e = t; e < HDIM * HDIM; e += 256)
        KVs[e >> 6][e & 63] = g_kv[(size_t)bh * (HDIM * HDIM) + e];
    if (t < 64) sks[t] = g_ks[(size_t)bh * HDIM + t];

    const size_t qbase = ((size_t)b * SEQ + n0) * DIMC + (size_t)h * HDIM;
    for (int f = t; f < 64 * 16; f += 256) {
        int r = f >> 4, c4 = (f & 15) * 4;
        float4 v = *(const float4*)(gq + qbase + (size_t)r * DIMC + c4);
        *(float4*)&Qs[r][c4] = v;
    }
    __syncthreads();

    if (t < 64) {
        float s = 0.f;
#pragma unroll
        for (int d = 0; d < 64; d++) s = fmaf(Qs[t][d], sks[d], s);
        dn[t] = fmaxf(s, 1e-6f);
    }
    __syncthreads();

    const int c  = t & 63;
    const int r0 = t >> 6;   // 0..3
    for (int rr = r0; rr < 64; rr += 4) {
        float acc = 0.f;
#pragma unroll
        for (int d = 0; d < 64; d++) acc = fmaf(Qs[rr][d], KVs[d][c], acc);
        out[((size_t)b * SEQ + n0 + rr) * DIMC + (size_t)h * HDIM + c] = acc / dn[rr];
    }
}

// ============================================================================
// K4: y = attn_out + x; LayerNorm(y) * gamma + beta.  One block per token.
// ============================================================================
__global__ __launch_bounds__(256) void ln_kernel(
    const float* __restrict__ x, const float* __restrict__ gamma,
    const float* __restrict__ beta, float* __restrict__ out)
{
    const int row = blockIdx.x;
    const int t = threadIdx.x;
    const size_t base = (size_t)row * DIMC;

    float4 o  = *(const float4*)(out + base + t * 4);
    float4 xi = *(const float4*)(x + base + t * 4);
    float y0 = o.x + xi.x, y1 = o.y + xi.y, y2 = o.z + xi.z, y3 = o.w + xi.w;

    float s  = y0 + y1 + y2 + y3;
    float sq = y0 * y0 + y1 * y1 + y2 * y2 + y3 * y3;
#pragma unroll
    for (int off = 16; off > 0; off >>= 1) {
        s  += __shfl_xor_sync(0xffffffffu, s, off);
        sq += __shfl_xor_sync(0xffffffffu, sq, off);
    }
    __shared__ float ws[8], wq[8], mv[2];
    const int warp = t >> 5, lane = t & 31;
    if (lane == 0) { ws[warp] = s; wq[warp] = sq; }
    __syncthreads();
    if (t == 0) {
        float ts = 0.f, tq = 0.f;
#pragma unroll
        for (int w = 0; w < 8; w++) { ts += ws[w]; tq += wq[w]; }
        float mean = ts * (1.0f / DIMC);
        float var  = tq * (1.0f / DIMC) - mean * mean;
        mv[0] = mean;
        mv[1] = rsqrtf(var + 1e-5f);
    }
    __syncthreads();
    const float mean = mv[0], rstd = mv[1];

    float4 g = *(const float4*)(gamma + t * 4);
    float4 be = *(const float4*)(beta + t * 4);
    float4 r;
    r.x = (y0 - mean) * rstd * g.x + be.x;
    r.y = (y1 - mean) * rstd * g.y + be.y;
    r.z = (y2 - mean) * rstd * g.z + be.z;
    r.w = (y3 - mean) * rstd * g.w + be.w;
    *(float4*)(out + base + t * 4) = r;
}

// ============================================================================
extern "C" void kernel_launch(void* const* d_in, const int* in_sizes, int n_in,
                              void* d_out, int out_size)
{
    const float* x     = (const float*)d_in[0];
    const float* Wq    = (const float*)d_in[1];
    const float* bq    = (const float*)d_in[2];
    const float* Wk    = (const float*)d_in[3];
    const float* bk    = (const float*)d_in[4];
    const float* Wv    = (const float*)d_in[5];
    const float* bv    = (const float*)d_in[6];
    const float* gamma = (const float*)d_in[7];
    const float* beta  = (const float*)d_in[8];
    float* out = (float*)d_out;

    float *pq, *pk, *pv;
    cudaGetSymbolAddress((void**)&pq, g_q);
    cudaGetSymbolAddress((void**)&pk, g_k);
    cudaGetSymbolAddress((void**)&pv, g_v);

    dim3 gg(DIMC / 128, M_TOT / 128);     // (8, 128)
    qkv_gemm<<<gg, 256>>>(x, Wq, bq, pq, 1);
    qkv_gemm<<<gg, 256>>>(x, Wk, bk, pk, 1);
    qkv_gemm<<<gg, 256>>>(x, Wv, bv, pv, 0);

    kv_partial<<<dim3(NSPLIT, BHN), 256>>>(pk, pv);
    kv_reduce<<<BHN, 256>>>();
    ctx_kernel<<<dim3(SEQ / 64, BHN), 256>>>(pq, out);
    ln_kernel<<<M_TOT, 256>>>(x, gamma, beta, out);
}

// round 10
// speedup vs baseline: 2.5734x; 2.5734x over previous
#include <cuda_runtime.h>
#include <cuda_fp16.h>
#include <cstdint>

#define DIMC   1024
#define HEADS  16
#define HDIM   64
#define BATCH  4
#define SEQ    4096
#define M_TOT  (BATCH * SEQ)      // 16384 tokens
#define BHN    (BATCH * HEADS)    // 64
#define NSPLIT 16

// ---- scratch (static device globals; no runtime allocation) ----
__device__ float g_q[(size_t)M_TOT * DIMC];
__device__ float g_k[(size_t)M_TOT * DIMC];
__device__ float g_v[(size_t)M_TOT * DIMC];
__device__ float g_kvp[(size_t)BHN * NSPLIT * HDIM * HDIM];
__device__ float g_ksp[(size_t)BHN * NSPLIT * HDIM];
__device__ float g_kv[(size_t)BHN * HDIM * HDIM];
__device__ float g_ks[(size_t)BHN * HDIM];

// ============================================================================
// mma.sync helpers (baseline PTX — compiles at compute_103, no 'a' needed)
// ============================================================================
#define LDMATRIX_X4(r0, r1, r2, r3, addr)                                     \
    asm volatile("ldmatrix.sync.aligned.m8n8.x4.shared.b16 {%0,%1,%2,%3}, [%4];" \
                 : "=r"(r0), "=r"(r1), "=r"(r2), "=r"(r3) : "r"(addr))

#define MMA16816(d0, d1, d2, d3, a0, a1, a2, a3, b0, b1)                      \
    asm volatile("mma.sync.aligned.m16n8k16.row.col.f32.f16.f16.f32 "         \
                 "{%0,%1,%2,%3},{%4,%5,%6,%7},{%8,%9},{%0,%1,%2,%3};"         \
                 : "+f"(d0), "+f"(d1), "+f"(d2), "+f"(d3)                     \
                 : "r"(a0), "r"(a1), "r"(a2), "r"(a3), "r"(b0), "r"(b1))

#define LDS32(r, addr)                                                        \
    asm volatile("ld.shared.b32 %0, [%1];" : "=r"(r) : "r"(addr))

__device__ __forceinline__ uint32_t smem_u32(const void* p) {
    uint32_t a;
    asm("{ .reg .u64 t; cvta.to.shared.u64 t, %1; cvt.u32.u64 %0, t; }"
        : "=r"(a) : "l"(p));
    return a;
}
__device__ __forceinline__ uint32_t pack_h2(float x, float y) {
    __half2 h = __floats2half2_rn(x, y);
    return *reinterpret_cast<uint32_t*>(&h);
}

// ============================================================================
// K1: projection GEMM via mma.sync fp16 (fp32 accumulate).
//   out[m, n] = relu?( sum_k X[m,k] * W[n,k] + bias[n] )
// CTA 128x128, BK=32, 8 warps as 2(M)x4(N), warp tile 64x32.
// smem rows padded to 40 halves (80B) -> conflict-light ldmatrix.
// ============================================================================
#define BM   128
#define BN   128
#define BKQ  32
#define ROWH 40                     // halves per smem row (32 + 8 pad)
#define ABUF (BM * ROWH)            // 5120 halves = 10240 B

__global__ __launch_bounds__(256) void qkv_gemm_hmma(
    const float* __restrict__ X, const float* __restrict__ W,
    const float* __restrict__ bias, float* __restrict__ out, int do_relu)
{
    __shared__ __half Asm[2][ABUF];
    __shared__ __half Bsm[2][ABUF];

    const int t    = threadIdx.x;
    const int wid  = t >> 5;
    const int lane = t & 31;
    const int m0   = blockIdx.y * BM;
    const int n0   = blockIdx.x * BN;
    const int wm   = (wid >> 2) * 64;   // warp M offset: 0 or 64
    const int wn   = (wid & 3) * 32;    // warp N offset: 0,32,64,96

    // global-load geometry: 32 rows x 8 float4 per pass, 4 passes -> 128 rows
    const int lrow = t >> 3;            // 0..31
    const int lf4  = t & 7;             // 0..7 (float4 within 128B k-chunk)

    const float* Ag = X + (size_t)(m0 + lrow) * DIMC + lf4 * 4;
    const float* Bg = W + (size_t)(n0 + lrow) * DIMC + lf4 * 4;

    float acc[4][4][4];
#pragma unroll
    for (int i = 0; i < 4; i++)
#pragma unroll
        for (int j = 0; j < 4; j++)
#pragma unroll
            for (int e = 0; e < 4; e++) acc[i][j][e] = 0.f;

    // ldmatrix lane mapping: rows (lane&15), col-half-block (lane>>4)*8
    const uint32_t a_base = smem_u32(&Asm[0][0]);
    const uint32_t b_base = smem_u32(&Bsm[0][0]);
    const uint32_t lm_off =
        (uint32_t)(((lane & 15) * ROWH + (lane >> 4) * 8) * 2);

    // B scalar-load geometry: n = lane>>2, k pair = (lane&3)*2
    const uint32_t bq_off =
        (uint32_t)(((lane >> 2) * ROWH + (lane & 3) * 2) * 2);

    float4 pa[4], pb[4];
#pragma unroll
    for (int rr = 0; rr < 4; rr++) {
        pa[rr] = *(const float4*)(Ag + (size_t)(rr * 32) * DIMC);
        pb[rr] = *(const float4*)(Bg + (size_t)(rr * 32) * DIMC);
    }

    const int NCH = DIMC / BKQ;         // 32 chunks
    for (int c = 0; c < NCH; c++) {
        const int buf = c & 1;
        // stage current chunk into smem (f32 -> half2 pack)
#pragma unroll
        for (int rr = 0; rr < 4; rr++) {
            const int row = lrow + rr * 32;
            *(uint2*)&Asm[buf][row * ROWH + lf4 * 4] =
                make_uint2(pack_h2(pa[rr].x, pa[rr].y),
                           pack_h2(pa[rr].z, pa[rr].w));
            *(uint2*)&Bsm[buf][row * ROWH + lf4 * 4] =
                make_uint2(pack_h2(pb[rr].x, pb[rr].y),
                           pack_h2(pb[rr].z, pb[rr].w));
        }
        __syncthreads();

        // prefetch next chunk
        if (c + 1 < NCH) {
            const float* An = Ag + (c + 1) * BKQ;
            const float* Bn = Bg + (c + 1) * BKQ;
#pragma unroll
            for (int rr = 0; rr < 4; rr++) {
                pa[rr] = *(const float4*)(An + (size_t)(rr * 32) * DIMC);
                pb[rr] = *(const float4*)(Bn + (size_t)(rr * 32) * DIMC);
            }
        }

        const uint32_t abase = a_base + buf * (ABUF * 2);
        const uint32_t bbase = b_base + buf * (ABUF * 2);

#pragma unroll
        for (int ks = 0; ks < 2; ks++) {
            uint32_t afr[4][4];
#pragma unroll
            for (int mf = 0; mf < 4; mf++) {
                const uint32_t addr = abase + lm_off +
                    (uint32_t)(((wm + mf * 16) * ROWH + ks * 16) * 2);
                LDMATRIX_X4(afr[mf][0], afr[mf][1], afr[mf][2], afr[mf][3], addr);
            }
            uint32_t bfr[4][2];
#pragma unroll
            for (int nf = 0; nf < 4; nf++) {
                const uint32_t addr = bbase + bq_off +
                    (uint32_t)(((wn + nf * 8) * ROWH + ks * 16) * 2);
                LDS32(bfr[nf][0], addr);
                LDS32(bfr[nf][1], addr + 16);
            }
#pragma unroll
            for (int mf = 0; mf < 4; mf++)
#pragma unroll
                for (int nf = 0; nf < 4; nf++)
                    MMA16816(acc[mf][nf][0], acc[mf][nf][1],
                             acc[mf][nf][2], acc[mf][nf][3],
                             afr[mf][0], afr[mf][1], afr[mf][2], afr[mf][3],
                             bfr[nf][0], bfr[nf][1]);
        }
        __syncthreads();
    }

    // epilogue: c0,c1 at (row, col..col+1); c2,c3 at (row+8, col..col+1)
    const int er = lane >> 2;           // 0..7
    const int ec = (lane & 3) * 2;      // 0,2,4,6
#pragma unroll
    for (int nf = 0; nf < 4; nf++) {
        const int col = n0 + wn + nf * 8 + ec;
        const float b0 = __ldg(bias + col);
        const float b1 = __ldg(bias + col + 1);
#pragma unroll
        for (int mf = 0; mf < 4; mf++) {
            const int row = m0 + wm + mf * 16 + er;
            float v0 = acc[mf][nf][0] + b0;
            float v1 = acc[mf][nf][1] + b1;
            float v2 = acc[mf][nf][2] + b0;
            float v3 = acc[mf][nf][3] + b1;
            if (do_relu) {
                v0 = fmaxf(v0, 0.f); v1 = fmaxf(v1, 0.f);
                v2 = fmaxf(v2, 0.f); v3 = fmaxf(v3, 0.f);
            }
            *(float2*)(out + (size_t)row * DIMC + col)       = make_float2(v0, v1);
            *(float2*)(out + (size_t)(row + 8) * DIMC + col) = make_float2(v2, v3);
        }
    }
}

// ============================================================================
// K2: partial kv[d][p] = sum_n k[n,d]*v[n,p], partial k_sum[d], per (b,h,split)
// ============================================================================
__global__ __launch_bounds__(256) void kv_partial(
    const float* __restrict__ gk, const float* __restrict__ gv)
{
    const int sp = blockIdx.x;          // 0..NSPLIT-1
    const int bh = blockIdx.y;          // 0..63
    const int b = bh >> 4, h = bh & 15;
    __shared__ float ks[16][64];
    __shared__ float vs[16][64];
    const int t = threadIdx.x;
    const int tr = t >> 4;              // 0..15 (d group)
    const int tc = t & 15;              // 0..15 (p group)

    float acc[4][4];
#pragma unroll
    for (int i = 0; i < 4; i++)
#pragma unroll
        for (int j = 0; j < 4; j++) acc[i][j] = 0.f;
    float ksum = 0.f;

    const size_t base = ((size_t)b * SEQ) * DIMC + (size_t)h * HDIM;
    const int n0 = sp * (SEQ / NSPLIT);
    const int lrow = t >> 4;            // 0..15
    const int lc4  = (t & 15) * 4;      // 0..60

    for (int nn = 0; nn < SEQ / NSPLIT; nn += 16) {
        const size_t g = base + (size_t)(n0 + nn + lrow) * DIMC + lc4;
        *(float4*)&ks[lrow][lc4] = *(const float4*)(gk + g);
        *(float4*)&vs[lrow][lc4] = *(const float4*)(gv + g);
        __syncthreads();
#pragma unroll
        for (int r = 0; r < 16; r++) {
            float4 kd = *(const float4*)&ks[r][tr * 4];
            float4 vd = *(const float4*)&vs[r][tc * 4];
            float ka[4] = {kd.x, kd.y, kd.z, kd.w};
            float va[4] = {vd.x, vd.y, vd.z, vd.w};
#pragma unroll
            for (int i = 0; i < 4; i++)
#pragma unroll
                for (int j = 0; j < 4; j++)
                    acc[i][j] = fmaf(ka[i], va[j], acc[i][j]);
        }
        if (t < 64) {
#pragma unroll
            for (int r = 0; r < 16; r++) ksum += ks[r][t];
        }
        __syncthreads();
    }

    float* o = g_kvp + ((size_t)bh * NSPLIT + sp) * (HDIM * HDIM);
#pragma unroll
    for (int i = 0; i < 4; i++)
#pragma unroll
        for (int j = 0; j < 4; j++)
            o[(tr * 4 + i) * HDIM + tc * 4 + j] = acc[i][j];
    if (t < 64) g_ksp[((size_t)bh * NSPLIT + sp) * HDIM + t] = ksum;
}

// ============================================================================
// K2b: reduce partials
// ============================================================================
__global__ __launch_bounds__(256) void kv_reduce()
{
    const int bh = blockIdx.x;
    const int t = threadIdx.x;
    for (int e = t; e < HDIM * HDIM; e += 256) {
        float s = 0.f;
#pragma unroll
        for (int sp = 0; sp < NSPLIT; sp++)
            s += g_kvp[((size_t)bh * NSPLIT + sp) * (HDIM * HDIM) + e];
        g_kv[(size_t)bh * (HDIM * HDIM) + e] = s;
    }
    if (t < HDIM) {
        float s = 0.f;
#pragma unroll
        for (int sp = 0; sp < NSPLIT; sp++)
            s += g_ksp[((size_t)bh * NSPLIT + sp) * HDIM + t];
        g_ks[(size_t)bh * HDIM + t] = s;
    }
}

// ============================================================================
// K3: ctx[n,p] = sum_d q[n,d]*kv[d,p];  denom = max(q . k_sum, 1e-6);
// ============================================================================
__global__ __launch_bounds__(256) void ctx_kernel(
    const float* __restrict__ gq, float* __restrict__ out)
{
    const int bh = blockIdx.y;
    const int b = bh >> 4, h = bh & 15;
    const int n0 = blockIdx.x * 64;
    __shared__ float KVs[64][64];
    __shared__ float Qs[64][64];
    __shared__ float sks[64];
    __shared__ float dn[64];
    const int t = threadIdx.x;

    for (int e = t; e < HDIM * HDIM; e += 256)
        KVs[e >> 6][e & 63] = g_kv[(size_t)bh * (HDIM * HDIM) + e];
    if (t < 64) sks[t] = g_ks[(size_t)bh * HDIM + t];

    const size_t qbase = ((size_t)b * SEQ + n0) * DIMC + (size_t)h * HDIM;
    for (int f = t; f < 64 * 16; f += 256) {
        int r = f >> 4, c4 = (f & 15) * 4;
        float4 v = *(const float4*)(gq + qbase + (size_t)r * DIMC + c4);
        *(float4*)&Qs[r][c4] = v;
    }
    __syncthreads();

    if (t < 64) {
        float s = 0.f;
#pragma unroll
        for (int d = 0; d < 64; d++) s = fmaf(Qs[t][d], sks[d], s);
        dn[t] = fmaxf(s, 1e-6f);
    }
    __syncthreads();

    const int c  = t & 63;
    const int r0 = t >> 6;   // 0..3
    for (int rr = r0; rr < 64; rr += 4) {
        float acc = 0.f;
#pragma unroll
        for (int d = 0; d < 64; d++) acc = fmaf(Qs[rr][d], KVs[d][c], acc);
        out[((size_t)b * SEQ + n0 + rr) * DIMC + (size_t)h * HDIM + c] = acc / dn[rr];
    }
}

// ============================================================================
// K4: y = attn_out + x; LayerNorm(y) * gamma + beta.  One block per token.
// ============================================================================
__global__ __launch_bounds__(256) void ln_kernel(
    const float* __restrict__ x, const float* __restrict__ gamma,
    const float* __restrict__ beta, float* __restrict__ out)
{
    const int row = blockIdx.x;
    const int t = threadIdx.x;
    const size_t base = (size_t)row * DIMC;

    float4 o  = *(const float4*)(out + base + t * 4);
    float4 xi = *(const float4*)(x + base + t * 4);
    float y0 = o.x + xi.x, y1 = o.y + xi.y, y2 = o.z + xi.z, y3 = o.w + xi.w;

    float s  = y0 + y1 + y2 + y3;
    float sq = y0 * y0 + y1 * y1 + y2 * y2 + y3 * y3;
#pragma unroll
    for (int off = 16; off > 0; off >>= 1) {
        s  += __shfl_xor_sync(0xffffffffu, s, off);
        sq += __shfl_xor_sync(0xffffffffu, sq, off);
    }
    __shared__ float ws[8], wq[8], mv[2];
    const int warp = t >> 5, lane = t & 31;
    if (lane == 0) { ws[warp] = s; wq[warp] = sq; }
    __syncthreads();
    if (t == 0) {
        float ts = 0.f, tq = 0.f;
#pragma unroll
        for (int w = 0; w < 8; w++) { ts += ws[w]; tq += wq[w]; }
        float mean = ts * (1.0f / DIMC);
        float var  = tq * (1.0f / DIMC) - mean * mean;
        mv[0] = mean;
        mv[1] = rsqrtf(var + 1e-5f);
    }
    __syncthreads();
    const float mean = mv[0], rstd = mv[1];

    float4 g = *(const float4*)(gamma + t * 4);
    float4 be = *(const float4*)(beta + t * 4);
    float4 r;
    r.x = (y0 - mean) * rstd * g.x + be.x;
    r.y = (y1 - mean) * rstd * g.y + be.y;
    r.z = (y2 - mean) * rstd * g.z + be.z;
    r.w = (y3 - mean) * rstd * g.w + be.w;
    *(float4*)(out + base + t * 4) = r;
}

// ============================================================================
extern "C" void kernel_launch(void* const* d_in, const int* in_sizes, int n_in,
                              void* d_out, int out_size)
{
    const float* x     = (const float*)d_in[0];
    const float* Wq    = (const float*)d_in[1];
    const float* bq    = (const float*)d_in[2];
    const float* Wk    = (const float*)d_in[3];
    const float* bk    = (const float*)d_in[4];
    const float* Wv    = (const float*)d_in[5];
    const float* bv    = (const float*)d_in[6];
    const float* gamma = (const float*)d_in[7];
    const float* beta  = (const float*)d_in[8];
    float* out = (float*)d_out;

    float *pq, *pk, *pv;
    cudaGetSymbolAddress((void**)&pq, g_q);
    cudaGetSymbolAddress((void**)&pk, g_k);
    cudaGetSymbolAddress((void**)&pv, g_v);

    dim3 gg(DIMC / BN, M_TOT / BM);       // (8, 128)
    qkv_gemm_hmma<<<gg, 256>>>(x, Wq, bq, pq, 1);
    qkv_gemm_hmma<<<gg, 256>>>(x, Wk, bk, pk, 1);
    qkv_gemm_hmma<<<gg, 256>>>(x, Wv, bv, pv, 0);

    kv_partial<<<dim3(NSPLIT, BHN), 256>>>(pk, pv);
    kv_reduce<<<BHN, 256>>>();
    ctx_kernel<<<dim3(SEQ / 64, BHN), 256>>>(pq, out);
    ln_kernel<<<M_TOT, 256>>>(x, gamma, beta, out);
}